// round 1
// baseline (speedup 1.0000x reference)
#include <cuda_runtime.h>
#include <math.h>

// Problem dims (fixed by the dataset)
#define BB 4
#define NN 96
#define TT 512
#define KK 12
#define GG 8

// ---------------- device scratch (no cudaMalloc allowed) ----------------
__device__ float g_lead[KK * 18];                       // per lead: L(3), e1(3), e2(3), Y(9)
__device__ float g_splat[(size_t)BB * KK * TT * 2 * 64];  // (B,K,T,2,8,8)

__device__ __forceinline__ float softplusf(float x) {
    return (x > 20.0f) ? x : log1pf(expf(x));
}

// ---------------- kernel 0: lead directions + camera bases + SH basis ----
__global__ void lead_kernel(const float* __restrict__ ra, const float* __restrict__ la,
                            const float* __restrict__ ll, const float* __restrict__ chest) {
    int k = threadIdx.x;
    if (k >= KK) return;
    float vx, vy, vz;
    float rax = ra[0], ray = ra[1], raz = ra[2];
    float lax = la[0], lay = la[1], laz = la[2];
    float llx = ll[0], lly = ll[1], llz = ll[2];
    switch (k) {
        case 0: vx = lax - rax; vy = lay - ray; vz = laz - raz; break;
        case 1: vx = llx - rax; vy = lly - ray; vz = llz - raz; break;
        case 2: vx = llx - lax; vy = lly - lay; vz = llz - laz; break;
        case 3: vx = rax - 0.5f * (lax + llx); vy = ray - 0.5f * (lay + lly); vz = raz - 0.5f * (laz + llz); break;
        case 4: vx = lax - 0.5f * (rax + llx); vy = lay - 0.5f * (ray + lly); vz = laz - 0.5f * (raz + llz); break;
        case 5: vx = llx - 0.5f * (rax + lax); vy = lly - 0.5f * (ray + lay); vz = llz - 0.5f * (raz + laz); break;
        default:
            vx = chest[(k - 6) * 3 + 0]; vy = chest[(k - 6) * 3 + 1]; vz = chest[(k - 6) * 3 + 2];
            break;
    }
    float n = sqrtf(vx * vx + vy * vy + vz * vz);
    float d = fmaxf(n, 1e-6f);
    float Lx = vx / d, Ly = vy / d, Lz = vz / d;
    // e1 = cross(L, (1,0,0)) = (0, Lz, -Ly); fallback cross(L,(0,1,0)) = (-Lz, 0, Lx)
    float e1x = 0.0f, e1y = Lz, e1z = -Ly;
    float n1 = sqrtf(e1y * e1y + e1z * e1z);
    if (n1 < 1e-4f) { e1x = -Lz; e1y = 0.0f; e1z = Lx; n1 = sqrtf(e1x * e1x + e1z * e1z); }
    float d1 = fmaxf(n1, 1e-6f);
    e1x /= d1; e1y /= d1; e1z /= d1;
    // e2 = normalize(cross(e1, L))
    float e2x = e1y * Lz - e1z * Ly;
    float e2y = e1z * Lx - e1x * Lz;
    float e2z = e1x * Ly - e1y * Lx;
    float n2 = sqrtf(e2x * e2x + e2y * e2y + e2z * e2z);
    float d2 = fmaxf(n2, 1e-6f);
    e2x /= d2; e2y /= d2; e2z /= d2;
    float* o = g_lead + k * 18;
    o[0] = Lx; o[1] = Ly; o[2] = Lz;
    o[3] = e1x; o[4] = e1y; o[5] = e1z;
    o[6] = e2x; o[7] = e2y; o[8] = e2z;
    o[9]  = 0.282095f;
    o[10] = -0.488603f * Ly;
    o[11] = 0.488603f * Lz;
    o[12] = -0.488603f * Lx;
    o[13] = 1.092548f * Lx * Ly;
    o[14] = -1.092548f * Ly * Lz;
    o[15] = 0.315392f * (3.0f * Lz * Lz - 1.0f);
    o[16] = -1.092548f * Lx * Lz;
    o[17] = 0.546274f * (Lx * Lx - Ly * Ly);
}

// ---------------- kernel 1: splat rasterization ----------------
// One block per (t, b); 12 warps, warp k owns lead k's 2x8x8 splat image.
#define NC 32

__global__ __launch_bounds__(384) void splat_kernel(
    const float* __restrict__ mu, const float* __restrict__ sigma0,
    const float* __restrict__ sigma_vel, const float* __restrict__ amplitude,
    const float* __restrict__ sh_base, const float* __restrict__ sh_vel,
    const float* __restrict__ p0, const float* __restrict__ p_vel,
    const float* __restrict__ tau_raw, const float* __restrict__ gam_raw) {
    __shared__ float  sLead[KK][18];
    __shared__ float2 sAA[NC][KK];        // (A, A*sh_proj)
    __shared__ float  sKu[NC][KK][9];     // pad 9 to dodge bank conflicts on STS
    __shared__ float  sKv[NC][KK][9];

    int t = blockIdx.x, b = blockIdx.y;
    int tid = threadIdx.x;
    if (tid < KK * 18) ((float*)sLead)[tid] = g_lead[tid];

    float tau = softplusf(tau_raw[0]) + 0.06f;
    float inv2tau2 = 0.5f / (tau * tau);
    float gamma = softplusf(gam_raw[0]) + 1e-6f;
    float tval = (float)t * (1.0f / (float)(TT - 1));

    int warp = tid >> 5, lane = tid & 31;
    int px0 = lane * 2;
    int hh = px0 >> 3, w0 = px0 & 7;
    float acc00 = 0.f, acc01 = 0.f, acc10 = 0.f, acc11 = 0.f;

    int nl = tid / KK, kk = tid - nl * KK;   // 384/12 = 32 exactly: all threads active
    __syncthreads();

    for (int c = 0; c < NN / NC; ++c) {
        // ---- phase 1: per-(n,k) scalars + separable kernels ----
        {
            int n = c * NC + nl;
            int bn = b * NN + n;
            float dt = tval - mu[bn];
            float sig = softplusf(sigma0[bn] + sigma_vel[bn] * dt) + 1e-3f;
            float z = dt / sig;
            float gauss = amplitude[bn] * __expf(-0.5f * z * z);
            float prx = p0[bn * 3 + 0] + p_vel[bn * 3 + 0] * dt;
            float pry = p0[bn * 3 + 1] + p_vel[bn * 3 + 1] * dt;
            float prz = p0[bn * 3 + 2] + p_vel[bn * 3 + 2] * dt;
            float nrm = fmaxf(sqrtf(prx * prx + pry * pry + prz * prz), 1e-8f);
            float th = tanhf(nrm);
            float sc = th / nrm;
            float ppx = prx * sc, ppy = pry * sc, ppz = prz * sc;
            const float* Ld = sLead[kk];
            float u = tanhf(ppx * Ld[3] + ppy * Ld[4] + ppz * Ld[5]);
            float v = tanhf(ppx * Ld[6] + ppy * Ld[7] + ppz * Ld[8]);
            float pn = fmaxf(th, 1e-8f);
            float cosl = (ppx * Ld[0] + ppy * Ld[1] + ppz * Ld[2]) / pn;
            float hem = fmaxf(cosl, 0.0f);
            float ccv = fminf(fmaxf(cosl, -1.0f + 1e-6f), 1.0f - 1e-6f);
            float theta = acosf(ccv);
            float weight = hem * __expf(-gamma * theta * theta);
            float A = gauss * weight;
            float shp = 0.0f;
            #pragma unroll
            for (int m = 0; m < 9; ++m)
                shp += (sh_base[bn * 9 + m] + sh_vel[bn * 9 + m] * dt) * Ld[9 + m];
            sAA[nl][kk] = make_float2(A, A * shp);
            #pragma unroll
            for (int g = 0; g < GG; ++g) {
                float gx = -1.0f + (float)g * (2.0f / 7.0f);
                float du = u - gx, dv = v - gx;
                sKu[nl][kk][g] = __expf(-inv2tau2 * du * du);
                sKv[nl][kk][g] = __expf(-inv2tau2 * dv * dv);
            }
        }
        __syncthreads();
        // ---- phase 2: warp k accumulates its splat image ----
        #pragma unroll 8
        for (int n2 = 0; n2 < NC; ++n2) {
            float2 aa = sAA[n2][warp];
            float kvh = sKv[n2][warp][hh];
            float ku0 = sKu[n2][warp][w0];
            float ku1 = sKu[n2][warp][w0 + 1];
            float tA = aa.x * kvh, tS = aa.y * kvh;
            acc00 = fmaf(tA, ku0, acc00);
            acc01 = fmaf(tA, ku1, acc01);
            acc10 = fmaf(tS, ku0, acc10);
            acc11 = fmaf(tS, ku1, acc11);
        }
        __syncthreads();
    }
    size_t base = ((size_t)((b * KK + warp) * TT + t)) * 128;
    g_splat[base + px0]       = acc00;
    g_splat[base + px0 + 1]   = acc01;
    g_splat[base + 64 + px0]     = acc10;
    g_splat[base + 64 + px0 + 1] = acc11;
}

// ---------------- kernel 2: shared CNN readout ----------------
// 2 tiles per 64-thread block (thread = pixel, reused across both tiles so each
// broadcast weight load from shared feeds 2 FMAs).
#define W2_OFF   0        // 9216
#define W1_OFF   9216     // 576
#define B1_OFF   9792     // 32
#define B2_OFF   9824     // 32
#define FC_OFF   9856     // 32
#define FCB_OFF  9888     // 1
#define IN_OFF   9892     // 2 tiles * 2 ch * 100
#define H1_OFF   10292    // 2 tiles * 32 ch * 100
#define RED_OFF  16692    // 4
#define SMEM_FLOATS 16696

__global__ __launch_bounds__(64) void cnn_kernel(
    const float* __restrict__ w1, const float* __restrict__ b1,
    const float* __restrict__ w2, const float* __restrict__ b2,
    const float* __restrict__ fcw, const float* __restrict__ fcb,
    float* __restrict__ out) {
    extern __shared__ float sm[];
    int tid = threadIdx.x;
    int tile0 = blockIdx.x * 2;

    // weight staging
    {
        float4* dst = (float4*)(sm + W2_OFF);
        const float4* src = (const float4*)w2;
        for (int i = tid; i < 9216 / 4; i += 64) dst[i] = src[i];
    }
    for (int i = tid; i < 576; i += 64) sm[W1_OFF + i] = w1[i];
    if (tid < 32) {
        sm[B1_OFF + tid] = b1[tid];
        sm[B2_OFF + tid] = b2[tid];
        sm[FC_OFF + tid] = fcw[tid];
    }
    if (tid == 0) sm[FCB_OFF] = fcb[0];
    for (int i = tid; i < 400; i += 64) sm[IN_OFF + i] = 0.0f;
    for (int i = tid; i < 6400; i += 64) sm[H1_OFF + i] = 0.0f;
    __syncthreads();

    int x = tid & 7, y = tid >> 3;
    #pragma unroll
    for (int tj = 0; tj < 2; ++tj) {
        const float* src = g_splat + (size_t)(tile0 + tj) * 128;
        sm[IN_OFF + (tj * 2 + 0) * 100 + (y + 1) * 10 + (x + 1)] = src[tid];
        sm[IN_OFF + (tj * 2 + 1) * 100 + (y + 1) * 10 + (x + 1)] = src[64 + tid];
    }
    __syncthreads();

    // conv1 (2->32) + exact GELU, write to padded shared
    #pragma unroll
    for (int tj = 0; tj < 2; ++tj) {
        float iv[18];
        #pragma unroll
        for (int c = 0; c < 2; ++c)
            #pragma unroll
            for (int r = 0; r < 3; ++r)
                #pragma unroll
                for (int q = 0; q < 3; ++q)
                    iv[c * 9 + r * 3 + q] = sm[IN_OFF + (tj * 2 + c) * 100 + (y + r) * 10 + (x + q)];
        #pragma unroll 4
        for (int oc = 0; oc < 32; ++oc) {
            float acc = sm[B1_OFF + oc];
            #pragma unroll
            for (int j = 0; j < 18; ++j) acc = fmaf(iv[j], sm[W1_OFF + oc * 18 + j], acc);
            sm[H1_OFF + (tj * 32 + oc) * 100 + (y + 1) * 10 + (x + 1)] = acc * normcdff(acc);
        }
    }
    __syncthreads();

    // conv2 (32->32): acc for both tiles in registers; weights broadcast from shared
    float acc2a[32], acc2b[32];
    #pragma unroll
    for (int oc = 0; oc < 32; ++oc) { acc2a[oc] = sm[B2_OFF + oc]; acc2b[oc] = acc2a[oc]; }
    #pragma unroll 1
    for (int ic = 0; ic < 32; ++ic) {
        float va[9], vb[9];
        #pragma unroll
        for (int r = 0; r < 3; ++r)
            #pragma unroll
            for (int q = 0; q < 3; ++q) {
                va[r * 3 + q] = sm[H1_OFF + ic * 100 + (y + r) * 10 + (x + q)];
                vb[r * 3 + q] = sm[H1_OFF + (32 + ic) * 100 + (y + r) * 10 + (x + q)];
            }
        #pragma unroll
        for (int oc = 0; oc < 32; ++oc) {
            const float* wrow = sm + W2_OFF + (oc * 32 + ic) * 9;
            #pragma unroll
            for (int j = 0; j < 9; ++j) {
                float wv = wrow[j];
                acc2a[oc] = fmaf(va[j], wv, acc2a[oc]);
                acc2b[oc] = fmaf(vb[j], wv, acc2b[oc]);
            }
        }
    }

    // GELU + fc dot, then mean over 64 pixels
    float sa = 0.0f, sb = 0.0f;
    #pragma unroll
    for (int oc = 0; oc < 32; ++oc) {
        float f = sm[FC_OFF + oc];
        float ha = acc2a[oc]; ha = ha * normcdff(ha);
        float hb = acc2b[oc]; hb = hb * normcdff(hb);
        sa = fmaf(ha, f, sa);
        sb = fmaf(hb, f, sb);
    }
    #pragma unroll
    for (int off = 16; off > 0; off >>= 1) {
        sa += __shfl_down_sync(0xffffffffu, sa, off);
        sb += __shfl_down_sync(0xffffffffu, sb, off);
    }
    int wp = tid >> 5;
    if ((tid & 31) == 0) { sm[RED_OFF + wp * 2 + 0] = sa; sm[RED_OFF + wp * 2 + 1] = sb; }
    __syncthreads();
    if (tid < 2) {
        float v = sm[RED_OFF + tid] + sm[RED_OFF + 2 + tid];
        v = v * (1.0f / 64.0f) + sm[FCB_OFF];
        int tile = tile0 + tid;
        int b = tile / (KK * TT);
        int rem = tile - b * (KK * TT);
        int k = rem / TT;
        int t = rem - k * TT;
        // faithful (B,T,12)-memory / (B,12,T)-view permutation
        out[(b * TT + t) * KK + k] = v;
    }
}

// ---------------- launch ----------------
extern "C" void kernel_launch(void* const* d_in, const int* in_sizes, int n_in,
                              void* d_out, int out_size) {
    const float* mu        = (const float*)d_in[0];
    const float* sigma0    = (const float*)d_in[1];
    const float* sigma_vel = (const float*)d_in[2];
    const float* amplitude = (const float*)d_in[3];
    const float* sh_base   = (const float*)d_in[4];
    const float* sh_vel    = (const float*)d_in[5];
    const float* p0        = (const float*)d_in[6];
    const float* p_vel     = (const float*)d_in[7];
    const float* tau_raw   = (const float*)d_in[8];
    const float* gam_raw   = (const float*)d_in[9];
    const float* limb_ra   = (const float*)d_in[10];
    const float* limb_la   = (const float*)d_in[11];
    const float* limb_ll   = (const float*)d_in[12];
    const float* chest     = (const float*)d_in[13];
    const float* conv1_w   = (const float*)d_in[14];
    const float* conv1_b   = (const float*)d_in[15];
    const float* conv2_w   = (const float*)d_in[16];
    const float* conv2_b   = (const float*)d_in[17];
    const float* fc_w      = (const float*)d_in[18];
    const float* fc_b      = (const float*)d_in[19];
    float* out = (float*)d_out;

    lead_kernel<<<1, 32>>>(limb_ra, limb_la, limb_ll, chest);
    splat_kernel<<<dim3(TT, BB), 384>>>(mu, sigma0, sigma_vel, amplitude,
                                        sh_base, sh_vel, p0, p_vel, tau_raw, gam_raw);
    size_t shbytes = SMEM_FLOATS * sizeof(float);
    cudaFuncSetAttribute(cnn_kernel, cudaFuncAttributeMaxDynamicSharedMemorySize, (int)shbytes);
    cnn_kernel<<<(BB * KK * TT) / 2, 64, shbytes>>>(conv1_w, conv1_b, conv2_w, conv2_b,
                                                    fc_w, fc_b, out);
}

// round 2
// speedup vs baseline: 2.1988x; 2.1988x over previous
#include <cuda_runtime.h>
#include <math.h>

// Problem dims (fixed by the dataset)
#define BB 4
#define NN 96
#define TT 512
#define KK 12
#define GG 8

// ---------------- device scratch (no cudaMalloc allowed) ----------------
__device__ float g_lead[KK * 18];                         // per lead: L(3), e1(3), e2(3), Y(9)
__device__ float g_splat[(size_t)BB * KK * TT * 128];     // (B,K,T,2,8,8)
__device__ float g_w2T[9216];                             // conv2 weights transposed [ic][j][oc]
__device__ float g_w1T[576];                              // conv1 weights transposed [c*9+j][oc]

typedef unsigned long long u64;

__device__ __forceinline__ u64 pack2(float x) {
    u64 r; asm("mov.b64 %0, {%1, %1};" : "=l"(r) : "f"(x)); return r;
}
__device__ __forceinline__ void ffma2(u64& d, u64 a, u64 b) {
    asm("fma.rn.f32x2 %0, %1, %2, %0;" : "+l"(d) : "l"(a), "l"(b));
}
__device__ __forceinline__ void unpack2(float& lo, float& hi, u64 v) {
    asm("mov.b64 {%0, %1}, %2;" : "=f"(lo), "=f"(hi) : "l"(v));
}

__device__ __forceinline__ float softplusf(float x) {
    return (x > 20.0f) ? x : log1pf(expf(x));
}

// ---------------- kernel 0: leads + weight transposes ----------------
__global__ void prep_kernel(const float* __restrict__ ra, const float* __restrict__ la,
                            const float* __restrict__ ll, const float* __restrict__ chest,
                            const float* __restrict__ w1, const float* __restrict__ w2) {
    int tid = threadIdx.x;
    // conv2 transpose: g_w2T[(ic*9+j)*32 + oc] = w2[oc*288 + ic*9 + j]
    for (int idx = tid; idx < 9216; idx += 256) {
        int oc = idx / 288;
        int rem = idx - oc * 288;   // ic*9 + j
        g_w2T[rem * 32 + oc] = w2[idx];
    }
    // conv1 transpose: g_w1T[r*32 + oc] = w1[oc*18 + r]
    for (int idx = tid; idx < 576; idx += 256) {
        int oc = idx / 18;
        int r = idx - oc * 18;
        g_w1T[r * 32 + oc] = w1[idx];
    }
    if (tid >= KK) return;
    int k = tid;
    float vx, vy, vz;
    float rax = ra[0], ray = ra[1], raz = ra[2];
    float lax = la[0], lay = la[1], laz = la[2];
    float llx = ll[0], lly = ll[1], llz = ll[2];
    switch (k) {
        case 0: vx = lax - rax; vy = lay - ray; vz = laz - raz; break;
        case 1: vx = llx - rax; vy = lly - ray; vz = llz - raz; break;
        case 2: vx = llx - lax; vy = lly - lay; vz = llz - laz; break;
        case 3: vx = rax - 0.5f * (lax + llx); vy = ray - 0.5f * (lay + lly); vz = raz - 0.5f * (laz + llz); break;
        case 4: vx = lax - 0.5f * (rax + llx); vy = lay - 0.5f * (ray + lly); vz = laz - 0.5f * (raz + llz); break;
        case 5: vx = llx - 0.5f * (rax + lax); vy = lly - 0.5f * (ray + lay); vz = llz - 0.5f * (raz + laz); break;
        default:
            vx = chest[(k - 6) * 3 + 0]; vy = chest[(k - 6) * 3 + 1]; vz = chest[(k - 6) * 3 + 2];
            break;
    }
    float n = sqrtf(vx * vx + vy * vy + vz * vz);
    float d = fmaxf(n, 1e-6f);
    float Lx = vx / d, Ly = vy / d, Lz = vz / d;
    float e1x = 0.0f, e1y = Lz, e1z = -Ly;
    float n1 = sqrtf(e1y * e1y + e1z * e1z);
    if (n1 < 1e-4f) { e1x = -Lz; e1y = 0.0f; e1z = Lx; n1 = sqrtf(e1x * e1x + e1z * e1z); }
    float d1 = fmaxf(n1, 1e-6f);
    e1x /= d1; e1y /= d1; e1z /= d1;
    float e2x = e1y * Lz - e1z * Ly;
    float e2y = e1z * Lx - e1x * Lz;
    float e2z = e1x * Ly - e1y * Lx;
    float n2 = sqrtf(e2x * e2x + e2y * e2y + e2z * e2z);
    float d2 = fmaxf(n2, 1e-6f);
    e2x /= d2; e2y /= d2; e2z /= d2;
    float* o = g_lead + k * 18;
    o[0] = Lx; o[1] = Ly; o[2] = Lz;
    o[3] = e1x; o[4] = e1y; o[5] = e1z;
    o[6] = e2x; o[7] = e2y; o[8] = e2z;
    o[9]  = 0.282095f;
    o[10] = -0.488603f * Ly;
    o[11] = 0.488603f * Lz;
    o[12] = -0.488603f * Lx;
    o[13] = 1.092548f * Lx * Ly;
    o[14] = -1.092548f * Ly * Lz;
    o[15] = 0.315392f * (3.0f * Lz * Lz - 1.0f);
    o[16] = -1.092548f * Lx * Lz;
    o[17] = 0.546274f * (Lx * Lx - Ly * Ly);
}

// ---------------- kernel 1: splat rasterization ----------------
#define NC 32

__global__ __launch_bounds__(384) void splat_kernel(
    const float* __restrict__ mu, const float* __restrict__ sigma0,
    const float* __restrict__ sigma_vel, const float* __restrict__ amplitude,
    const float* __restrict__ sh_base, const float* __restrict__ sh_vel,
    const float* __restrict__ p0, const float* __restrict__ p_vel,
    const float* __restrict__ tau_raw, const float* __restrict__ gam_raw) {
    __shared__ float  sLead[KK][18];
    __shared__ float2 sAA[NC][KK];
    __shared__ float  sKu[NC][KK][9];
    __shared__ float  sKv[NC][KK][9];

    int t = blockIdx.x, b = blockIdx.y;
    int tid = threadIdx.x;
    if (tid < KK * 18) ((float*)sLead)[tid] = g_lead[tid];

    float tau = softplusf(tau_raw[0]) + 0.06f;
    float inv2tau2 = 0.5f / (tau * tau);
    float gamma = softplusf(gam_raw[0]) + 1e-6f;
    float tval = (float)t * (1.0f / (float)(TT - 1));

    int warp = tid >> 5, lane = tid & 31;
    int px0 = lane * 2;
    int hh = px0 >> 3, w0 = px0 & 7;
    float acc00 = 0.f, acc01 = 0.f, acc10 = 0.f, acc11 = 0.f;

    int nl = tid / KK, kk = tid - nl * KK;
    __syncthreads();

    for (int c = 0; c < NN / NC; ++c) {
        {
            int n = c * NC + nl;
            int bn = b * NN + n;
            float dt = tval - mu[bn];
            float sig = softplusf(sigma0[bn] + sigma_vel[bn] * dt) + 1e-3f;
            float z = dt / sig;
            float gauss = amplitude[bn] * __expf(-0.5f * z * z);
            float prx = p0[bn * 3 + 0] + p_vel[bn * 3 + 0] * dt;
            float pry = p0[bn * 3 + 1] + p_vel[bn * 3 + 1] * dt;
            float prz = p0[bn * 3 + 2] + p_vel[bn * 3 + 2] * dt;
            float nrm = fmaxf(sqrtf(prx * prx + pry * pry + prz * prz), 1e-8f);
            float th = tanhf(nrm);
            float sc = th / nrm;
            float ppx = prx * sc, ppy = pry * sc, ppz = prz * sc;
            const float* Ld = sLead[kk];
            float u = tanhf(ppx * Ld[3] + ppy * Ld[4] + ppz * Ld[5]);
            float v = tanhf(ppx * Ld[6] + ppy * Ld[7] + ppz * Ld[8]);
            float pn = fmaxf(th, 1e-8f);
            float cosl = (ppx * Ld[0] + ppy * Ld[1] + ppz * Ld[2]) / pn;
            float hem = fmaxf(cosl, 0.0f);
            float ccv = fminf(fmaxf(cosl, -1.0f + 1e-6f), 1.0f - 1e-6f);
            float theta = acosf(ccv);
            float weight = hem * __expf(-gamma * theta * theta);
            float A = gauss * weight;
            float shp = 0.0f;
            #pragma unroll
            for (int m = 0; m < 9; ++m)
                shp += (sh_base[bn * 9 + m] + sh_vel[bn * 9 + m] * dt) * Ld[9 + m];
            sAA[nl][kk] = make_float2(A, A * shp);
            #pragma unroll
            for (int g = 0; g < GG; ++g) {
                float gx = -1.0f + (float)g * (2.0f / 7.0f);
                float du = u - gx, dv = v - gx;
                sKu[nl][kk][g] = __expf(-inv2tau2 * du * du);
                sKv[nl][kk][g] = __expf(-inv2tau2 * dv * dv);
            }
        }
        __syncthreads();
        #pragma unroll 8
        for (int n2 = 0; n2 < NC; ++n2) {
            float2 aa = sAA[n2][warp];
            float kvh = sKv[n2][warp][hh];
            float ku0 = sKu[n2][warp][w0];
            float ku1 = sKu[n2][warp][w0 + 1];
            float tA = aa.x * kvh, tS = aa.y * kvh;
            acc00 = fmaf(tA, ku0, acc00);
            acc01 = fmaf(tA, ku1, acc01);
            acc10 = fmaf(tS, ku0, acc10);
            acc11 = fmaf(tS, ku1, acc11);
        }
        __syncthreads();
    }
    size_t base = ((size_t)((b * KK + warp) * TT + t)) * 128;
    g_splat[base + px0]          = acc00;
    g_splat[base + px0 + 1]      = acc01;
    g_splat[base + 64 + px0]     = acc10;
    g_splat[base + 64 + px0 + 1] = acc11;
}

// ---------------- kernel 2: CNN readout (packed f32x2, oc-pair accumulators) --
// 128 threads, 4 tiles per block; thread = pixel, handles 2 tiles (its group's pair).
#define W2T_OFF  0        // 9216  [ic][j][oc] rows of 32 floats (128B aligned)
#define W1T_OFF  9216     // 576   [c*9+j][oc]
#define B1_OFF   9792     // 32
#define B2_OFF   9824     // 32
#define FC_OFF   9856     // 32
#define FCB_OFF  9888     // 1
#define IN_OFF   9892     // 4 tiles * 2 ch * 100  (padded 10x10)
#define H1_OFF   10696    // 4 tiles * 32 ch * 100 (padded 10x10)
#define RED_OFF  23496    // 8
#define SMEM_FLOATS 23504

__global__ __launch_bounds__(128) void cnn_kernel(
    const float* __restrict__ b1g, const float* __restrict__ b2g,
    const float* __restrict__ fcw, const float* __restrict__ fcb,
    float* __restrict__ out) {
    extern __shared__ float sm[];
    int tid = threadIdx.x;
    int tile0 = blockIdx.x * 4;
    int group = tid >> 6;           // 0/1 -> tiles {2g, 2g+1}
    int p = tid & 63;
    int x = p & 7, y = p >> 3;

    // ---- phase A: zero padded buffers + stage weights ----
    for (int i = tid; i < 800; i += 128) sm[IN_OFF + i] = 0.0f;
    for (int i = tid; i < 12800; i += 128) sm[H1_OFF + i] = 0.0f;
    {
        float4* dst = (float4*)(sm + W2T_OFF);
        const float4* src = (const float4*)g_w2T;
        for (int i = tid; i < 2304; i += 128) dst[i] = src[i];
        float4* dst1 = (float4*)(sm + W1T_OFF);
        const float4* src1 = (const float4*)g_w1T;
        for (int i = tid; i < 144; i += 128) dst1[i] = src1[i];
    }
    if (tid < 32) {
        sm[B1_OFF + tid] = b1g[tid];
        sm[B2_OFF + tid] = b2g[tid];
        sm[FC_OFF + tid] = fcw[tid];
    }
    if (tid == 0) sm[FCB_OFF] = fcb[0];
    __syncthreads();

    // ---- phase B: stage splat inputs into padded IN ----
    for (int i = tid; i < 512; i += 128) {
        int tj = i >> 7;
        int e = i & 127;
        int ch = e >> 6;
        int pp = e & 63;
        int py = pp >> 3, px = pp & 7;
        sm[IN_OFF + (tj * 2 + ch) * 100 + (py + 1) * 10 + (px + 1)] =
            g_splat[(size_t)(tile0 + tj) * 128 + e];
    }
    __syncthreads();

    // ---- conv1 (2->32), packed over oc pairs, 2 tiles per thread ----
    {
        float iv0[18], iv1[18];
        int ibase0 = IN_OFF + (group * 2 + 0) * 200 + y * 10 + x;
        int ibase1 = IN_OFF + (group * 2 + 1) * 200 + y * 10 + x;
        #pragma unroll
        for (int c = 0; c < 2; ++c)
            #pragma unroll
            for (int r = 0; r < 3; ++r)
                #pragma unroll
                for (int q = 0; q < 3; ++q) {
                    iv0[c * 9 + r * 3 + q] = sm[ibase0 + c * 100 + r * 10 + q];
                    iv1[c * 9 + r * 3 + q] = sm[ibase1 + c * 100 + r * 10 + q];
                }
        u64 c1a[16], c1b[16];
        #pragma unroll
        for (int q = 0; q < 16; ++q) {
            u64 bb = ((const u64*)(sm + B1_OFF))[q];
            c1a[q] = bb; c1b[q] = bb;
        }
        #pragma unroll
        for (int j = 0; j < 18; ++j) {
            u64 pa0 = pack2(iv0[j]);
            u64 pa1 = pack2(iv1[j]);
            const ulonglong2* wv = (const ulonglong2*)(sm + W1T_OFF + j * 32);
            #pragma unroll
            for (int q = 0; q < 8; ++q) {
                ulonglong2 w = wv[q];
                ffma2(c1a[2 * q], pa0, w.x); ffma2(c1a[2 * q + 1], pa0, w.y);
                ffma2(c1b[2 * q], pa1, w.x); ffma2(c1b[2 * q + 1], pa1, w.y);
            }
        }
        int h0 = H1_OFF + (group * 2 + 0) * 3200 + (y + 1) * 10 + (x + 1);
        int h1b_ = H1_OFF + (group * 2 + 1) * 3200 + (y + 1) * 10 + (x + 1);
        #pragma unroll
        for (int q = 0; q < 16; ++q) {
            float lo, hi;
            unpack2(lo, hi, c1a[q]);
            sm[h0 + (2 * q) * 100] = lo * normcdff(lo);
            sm[h0 + (2 * q + 1) * 100] = hi * normcdff(hi);
            unpack2(lo, hi, c1b[q]);
            sm[h1b_ + (2 * q) * 100] = lo * normcdff(lo);
            sm[h1b_ + (2 * q + 1) * 100] = hi * normcdff(hi);
        }
    }
    __syncthreads();

    // ---- conv2 (32->32), packed f32x2 over oc pairs ----
    u64 acc0[16], acc1[16];
    #pragma unroll
    for (int q = 0; q < 16; ++q) {
        u64 bb = ((const u64*)(sm + B2_OFF))[q];
        acc0[q] = bb; acc1[q] = bb;
    }
    {
        const float* h1a = sm + H1_OFF + (group * 2 + 0) * 3200;
        const float* h1b = sm + H1_OFF + (group * 2 + 1) * 3200;
        int pbase = y * 10 + x;
        #pragma unroll 1
        for (int ic = 0; ic < 32; ++ic) {
            float a0[9], a1[9];
            int base = ic * 100 + pbase;
            #pragma unroll
            for (int r = 0; r < 3; ++r)
                #pragma unroll
                for (int q = 0; q < 3; ++q) {
                    a0[r * 3 + q] = h1a[base + r * 10 + q];
                    a1[r * 3 + q] = h1b[base + r * 10 + q];
                }
            const float* wrow = sm + W2T_OFF + ic * 288;
            #pragma unroll
            for (int j = 0; j < 9; ++j) {
                u64 pa0 = pack2(a0[j]);
                u64 pa1 = pack2(a1[j]);
                const ulonglong2* wv = (const ulonglong2*)(wrow + j * 32);
                #pragma unroll
                for (int q = 0; q < 8; ++q) {
                    ulonglong2 w = wv[q];
                    ffma2(acc0[2 * q], pa0, w.x); ffma2(acc0[2 * q + 1], pa0, w.y);
                    ffma2(acc1[2 * q], pa1, w.x); ffma2(acc1[2 * q + 1], pa1, w.y);
                }
            }
        }
    }

    // ---- GELU + fc dot per pixel, then mean over 64 pixels ----
    float sa = 0.0f, sb = 0.0f;
    #pragma unroll
    for (int q = 0; q < 16; ++q) {
        float f0 = sm[FC_OFF + 2 * q], f1 = sm[FC_OFF + 2 * q + 1];
        float lo, hi;
        unpack2(lo, hi, acc0[q]);
        sa = fmaf(lo * normcdff(lo), f0, sa);
        sa = fmaf(hi * normcdff(hi), f1, sa);
        unpack2(lo, hi, acc1[q]);
        sb = fmaf(lo * normcdff(lo), f0, sb);
        sb = fmaf(hi * normcdff(hi), f1, sb);
    }
    #pragma unroll
    for (int off = 16; off > 0; off >>= 1) {
        sa += __shfl_down_sync(0xffffffffu, sa, off);
        sb += __shfl_down_sync(0xffffffffu, sb, off);
    }
    int w = tid >> 5;  // warp 0..3
    if ((tid & 31) == 0) {
        sm[RED_OFF + (w >> 1) * 4 + (w & 1) * 2 + 0] = sa;
        sm[RED_OFF + (w >> 1) * 4 + (w & 1) * 2 + 1] = sb;
    }
    __syncthreads();
    if (tid < 4) {
        int grp = tid >> 1, sel = tid & 1;
        float v = sm[RED_OFF + grp * 4 + sel] + sm[RED_OFF + grp * 4 + 2 + sel];
        v = v * (1.0f / 64.0f) + sm[FCB_OFF];
        int tile = tile0 + tid;
        int b = tile / (KK * TT);
        int rem = tile - b * (KK * TT);
        int k = rem / TT;
        int t = rem - k * TT;
        out[(b * TT + t) * KK + k] = v;
    }
}

// ---------------- launch ----------------
extern "C" void kernel_launch(void* const* d_in, const int* in_sizes, int n_in,
                              void* d_out, int out_size) {
    const float* mu        = (const float*)d_in[0];
    const float* sigma0    = (const float*)d_in[1];
    const float* sigma_vel = (const float*)d_in[2];
    const float* amplitude = (const float*)d_in[3];
    const float* sh_base   = (const float*)d_in[4];
    const float* sh_vel    = (const float*)d_in[5];
    const float* p0        = (const float*)d_in[6];
    const float* p_vel     = (const float*)d_in[7];
    const float* tau_raw   = (const float*)d_in[8];
    const float* gam_raw   = (const float*)d_in[9];
    const float* limb_ra   = (const float*)d_in[10];
    const float* limb_la   = (const float*)d_in[11];
    const float* limb_ll   = (const float*)d_in[12];
    const float* chest     = (const float*)d_in[13];
    const float* conv1_w   = (const float*)d_in[14];
    const float* conv1_b   = (const float*)d_in[15];
    const float* conv2_w   = (const float*)d_in[16];
    const float* conv2_b   = (const float*)d_in[17];
    const float* fc_w      = (const float*)d_in[18];
    const float* fc_b      = (const float*)d_in[19];
    float* out = (float*)d_out;

    prep_kernel<<<1, 256>>>(limb_ra, limb_la, limb_ll, chest, conv1_w, conv2_w);
    splat_kernel<<<dim3(TT, BB), 384>>>(mu, sigma0, sigma_vel, amplitude,
                                        sh_base, sh_vel, p0, p_vel, tau_raw, gam_raw);
    size_t shbytes = SMEM_FLOATS * sizeof(float);
    cudaFuncSetAttribute(cnn_kernel, cudaFuncAttributeMaxDynamicSharedMemorySize, (int)shbytes);
    cnn_kernel<<<(BB * KK * TT) / 4, 128, shbytes>>>(conv1_b, conv2_b, fc_w, fc_b, out);
}

// round 3
// speedup vs baseline: 3.0076x; 1.3678x over previous
#include <cuda_runtime.h>
#include <math.h>

// Problem dims (fixed by the dataset)
#define BB 4
#define NN 96
#define TT 512
#define KK 12
#define GG 8

// ---------------- device scratch (no cudaMalloc allowed) ----------------
__device__ float g_lead[KK * 18];                         // per lead: L(3), e1(3), e2(3), Y(9)
__device__ float g_splat[(size_t)BB * KK * TT * 128];     // (B,K,T,2,8,8)
__device__ float g_w2T[9216];                             // conv2 weights transposed [ic][j][oc]
__device__ float g_w1T[576];                              // conv1 weights transposed [c*9+j][oc]

typedef unsigned long long u64;

__device__ __forceinline__ u64 pack2(float x) {
    u64 r; asm("mov.b64 %0, {%1, %1};" : "=l"(r) : "f"(x)); return r;
}
__device__ __forceinline__ void ffma2(u64& d, u64 a, u64 b) {
    asm("fma.rn.f32x2 %0, %1, %2, %0;" : "+l"(d) : "l"(a), "l"(b));
}
__device__ __forceinline__ void unpack2(float& lo, float& hi, u64 v) {
    asm("mov.b64 {%0, %1}, %2;" : "=f"(lo), "=f"(hi) : "l"(v));
}

__device__ __forceinline__ float softplusf(float x) {
    return (x > 20.0f) ? x : log1pf(expf(x));
}

// ---------------- kernel 0: leads + weight transposes ----------------
__global__ void prep_kernel(const float* __restrict__ ra, const float* __restrict__ la,
                            const float* __restrict__ ll, const float* __restrict__ chest,
                            const float* __restrict__ w1, const float* __restrict__ w2) {
    int tid = threadIdx.x;
    for (int idx = tid; idx < 9216; idx += 256) {
        int oc = idx / 288;
        int rem = idx - oc * 288;   // ic*9 + j
        g_w2T[rem * 32 + oc] = w2[idx];
    }
    for (int idx = tid; idx < 576; idx += 256) {
        int oc = idx / 18;
        int r = idx - oc * 18;
        g_w1T[r * 32 + oc] = w1[idx];
    }
    if (tid >= KK) return;
    int k = tid;
    float vx, vy, vz;
    float rax = ra[0], ray = ra[1], raz = ra[2];
    float lax = la[0], lay = la[1], laz = la[2];
    float llx = ll[0], lly = ll[1], llz = ll[2];
    switch (k) {
        case 0: vx = lax - rax; vy = lay - ray; vz = laz - raz; break;
        case 1: vx = llx - rax; vy = lly - ray; vz = llz - raz; break;
        case 2: vx = llx - lax; vy = lly - lay; vz = llz - laz; break;
        case 3: vx = rax - 0.5f * (lax + llx); vy = ray - 0.5f * (lay + lly); vz = raz - 0.5f * (laz + llz); break;
        case 4: vx = lax - 0.5f * (rax + llx); vy = lay - 0.5f * (ray + lly); vz = laz - 0.5f * (raz + llz); break;
        case 5: vx = llx - 0.5f * (rax + lax); vy = lly - 0.5f * (ray + lay); vz = llz - 0.5f * (raz + laz); break;
        default:
            vx = chest[(k - 6) * 3 + 0]; vy = chest[(k - 6) * 3 + 1]; vz = chest[(k - 6) * 3 + 2];
            break;
    }
    float n = sqrtf(vx * vx + vy * vy + vz * vz);
    float d = fmaxf(n, 1e-6f);
    float Lx = vx / d, Ly = vy / d, Lz = vz / d;
    float e1x = 0.0f, e1y = Lz, e1z = -Ly;
    float n1 = sqrtf(e1y * e1y + e1z * e1z);
    if (n1 < 1e-4f) { e1x = -Lz; e1y = 0.0f; e1z = Lx; n1 = sqrtf(e1x * e1x + e1z * e1z); }
    float d1 = fmaxf(n1, 1e-6f);
    e1x /= d1; e1y /= d1; e1z /= d1;
    float e2x = e1y * Lz - e1z * Ly;
    float e2y = e1z * Lx - e1x * Lz;
    float e2z = e1x * Ly - e1y * Lx;
    float n2 = sqrtf(e2x * e2x + e2y * e2y + e2z * e2z);
    float d2 = fmaxf(n2, 1e-6f);
    e2x /= d2; e2y /= d2; e2z /= d2;
    float* o = g_lead + k * 18;
    o[0] = Lx; o[1] = Ly; o[2] = Lz;
    o[3] = e1x; o[4] = e1y; o[5] = e1z;
    o[6] = e2x; o[7] = e2y; o[8] = e2z;
    o[9]  = 0.282095f;
    o[10] = -0.488603f * Ly;
    o[11] = 0.488603f * Lz;
    o[12] = -0.488603f * Lx;
    o[13] = 1.092548f * Lx * Ly;
    o[14] = -1.092548f * Ly * Lz;
    o[15] = 0.315392f * (3.0f * Lz * Lz - 1.0f);
    o[16] = -1.092548f * Lx * Lz;
    o[17] = 0.546274f * (Lx * Lx - Ly * Ly);
}

// ---------------- kernel 1: splat rasterization ----------------
#define NC 32

__global__ __launch_bounds__(384) void splat_kernel(
    const float* __restrict__ mu, const float* __restrict__ sigma0,
    const float* __restrict__ sigma_vel, const float* __restrict__ amplitude,
    const float* __restrict__ sh_base, const float* __restrict__ sh_vel,
    const float* __restrict__ p0, const float* __restrict__ p_vel,
    const float* __restrict__ tau_raw, const float* __restrict__ gam_raw) {
    __shared__ float  sLead[KK][18];
    __shared__ float2 sAA[NC][KK];
    __shared__ float  sKu[NC][KK][9];
    __shared__ float  sKv[NC][KK][9];

    int t = blockIdx.x, b = blockIdx.y;
    int tid = threadIdx.x;
    if (tid < KK * 18) ((float*)sLead)[tid] = g_lead[tid];

    float tau = softplusf(tau_raw[0]) + 0.06f;
    float inv2tau2 = 0.5f / (tau * tau);
    float gamma = softplusf(gam_raw[0]) + 1e-6f;
    float tval = (float)t * (1.0f / (float)(TT - 1));

    int warp = tid >> 5, lane = tid & 31;
    int px0 = lane * 2;
    int hh = px0 >> 3, w0 = px0 & 7;
    float acc00 = 0.f, acc01 = 0.f, acc10 = 0.f, acc11 = 0.f;

    int nl = tid / KK, kk = tid - nl * KK;
    __syncthreads();

    for (int c = 0; c < NN / NC; ++c) {
        {
            int n = c * NC + nl;
            int bn = b * NN + n;
            float dt = tval - mu[bn];
            float sig = softplusf(sigma0[bn] + sigma_vel[bn] * dt) + 1e-3f;
            float z = dt / sig;
            float gauss = amplitude[bn] * __expf(-0.5f * z * z);
            float prx = p0[bn * 3 + 0] + p_vel[bn * 3 + 0] * dt;
            float pry = p0[bn * 3 + 1] + p_vel[bn * 3 + 1] * dt;
            float prz = p0[bn * 3 + 2] + p_vel[bn * 3 + 2] * dt;
            float nrm = fmaxf(sqrtf(prx * prx + pry * pry + prz * prz), 1e-8f);
            float th = tanhf(nrm);
            float sc = th / nrm;
            float ppx = prx * sc, ppy = pry * sc, ppz = prz * sc;
            const float* Ld = sLead[kk];
            float u = tanhf(ppx * Ld[3] + ppy * Ld[4] + ppz * Ld[5]);
            float v = tanhf(ppx * Ld[6] + ppy * Ld[7] + ppz * Ld[8]);
            float pn = fmaxf(th, 1e-8f);
            float cosl = (ppx * Ld[0] + ppy * Ld[1] + ppz * Ld[2]) / pn;
            float hem = fmaxf(cosl, 0.0f);
            float ccv = fminf(fmaxf(cosl, -1.0f + 1e-6f), 1.0f - 1e-6f);
            float theta = acosf(ccv);
            float weight = hem * __expf(-gamma * theta * theta);
            float A = gauss * weight;
            float shp = 0.0f;
            #pragma unroll
            for (int m = 0; m < 9; ++m)
                shp += (sh_base[bn * 9 + m] + sh_vel[bn * 9 + m] * dt) * Ld[9 + m];
            sAA[nl][kk] = make_float2(A, A * shp);
            #pragma unroll
            for (int g = 0; g < GG; ++g) {
                float gx = -1.0f + (float)g * (2.0f / 7.0f);
                float du = u - gx, dv = v - gx;
                sKu[nl][kk][g] = __expf(-inv2tau2 * du * du);
                sKv[nl][kk][g] = __expf(-inv2tau2 * dv * dv);
            }
        }
        __syncthreads();
        #pragma unroll 8
        for (int n2 = 0; n2 < NC; ++n2) {
            float2 aa = sAA[n2][warp];
            float kvh = sKv[n2][warp][hh];
            float ku0 = sKu[n2][warp][w0];
            float ku1 = sKu[n2][warp][w0 + 1];
            float tA = aa.x * kvh, tS = aa.y * kvh;
            acc00 = fmaf(tA, ku0, acc00);
            acc01 = fmaf(tA, ku1, acc01);
            acc10 = fmaf(tS, ku0, acc10);
            acc11 = fmaf(tS, ku1, acc11);
        }
        __syncthreads();
    }
    size_t base = ((size_t)((b * KK + warp) * TT + t)) * 128;
    g_splat[base + px0]          = acc00;
    g_splat[base + px0 + 1]      = acc01;
    g_splat[base + 64 + px0]     = acc10;
    g_splat[base + 64 + px0 + 1] = acc11;
}

// ---------------- kernel 2: CNN readout (chunked H1 for occupancy) ----------
// 128 threads, 4 tiles per block; thread = pixel, handles 2 tiles.
// conv1 -> conv2 processed in four 8-input-channel chunks through a small
// shared H1 buffer so the block fits 55.6KB smem and <=128 regs -> 4 blocks/SM.
#define W2T_OFF  0        // 9216  [ic][j][oc]
#define W1T_OFF  9216     // 576   [c*9+j][oc]
#define B1_OFF   9792     // 32
#define B2_OFF   9824     // 32
#define FC_OFF   9856     // 32
#define FCB_OFF  9888     // 1 (+3 pad)
#define IN_OFF   9892     // 4 tiles * 2 ch * 100  (padded 10x10)
#define H1C_OFF  10692    // 4 tiles * 8 ch * 100 (one chunk)
#define RED_OFF  13892    // 8
#define SMEM_FLOATS 13900

__global__ __launch_bounds__(128, 4) void cnn_kernel(
    const float* __restrict__ b1g, const float* __restrict__ b2g,
    const float* __restrict__ fcw, const float* __restrict__ fcb,
    float* __restrict__ out) {
    extern __shared__ float sm[];
    int tid = threadIdx.x;
    int tile0 = blockIdx.x * 4;
    int group = tid >> 6;           // 0/1 -> tiles {2g, 2g+1}
    int p = tid & 63;
    int x = p & 7, y = p >> 3;

    // ---- stage weights + zero padded buffers ----
    for (int i = tid; i < 800; i += 128) sm[IN_OFF + i] = 0.0f;
    for (int i = tid; i < 3200; i += 128) sm[H1C_OFF + i] = 0.0f;
    {
        float4* dst = (float4*)(sm + W2T_OFF);
        const float4* src = (const float4*)g_w2T;
        for (int i = tid; i < 2304; i += 128) dst[i] = src[i];
        float4* dst1 = (float4*)(sm + W1T_OFF);
        const float4* src1 = (const float4*)g_w1T;
        for (int i = tid; i < 144; i += 128) dst1[i] = src1[i];
    }
    if (tid < 32) {
        sm[B1_OFF + tid] = b1g[tid];
        sm[B2_OFF + tid] = b2g[tid];
        sm[FC_OFF + tid] = fcw[tid];
    }
    if (tid == 0) sm[FCB_OFF] = fcb[0];

    // ---- stage splat inputs into padded IN ----
    __syncthreads();
    for (int i = tid; i < 512; i += 128) {
        int tj = i >> 7;
        int e = i & 127;
        int ch = e >> 6;
        int pp = e & 63;
        int py = pp >> 3, px = pp & 7;
        sm[IN_OFF + (tj * 2 + ch) * 100 + (py + 1) * 10 + (px + 1)] =
            g_splat[(size_t)(tile0 + tj) * 128 + e];
    }
    __syncthreads();

    // conv2 accumulators (persist across chunks): 32 oc as 16 pairs, 2 tiles
    u64 acc0[16], acc1[16];
    #pragma unroll
    for (int q = 0; q < 16; ++q) {
        u64 bb = ((const u64*)(sm + B2_OFF))[q];
        acc0[q] = bb; acc1[q] = bb;
    }

    int ibase0 = IN_OFF + (group * 2 + 0) * 200 + y * 10 + x;
    int ibase1 = IN_OFF + (group * 2 + 1) * 200 + y * 10 + x;
    int hw0 = H1C_OFF + (group * 2 + 0) * 800 + (y + 1) * 10 + (x + 1);
    int hw1 = H1C_OFF + (group * 2 + 1) * 800 + (y + 1) * 10 + (x + 1);
    int pbase = y * 10 + x;

    #pragma unroll 1
    for (int cc = 0; cc < 4; ++cc) {
        // ---- conv1 for 8 output channels (this chunk) ----
        {
            u64 c1a[4], c1b[4];
            #pragma unroll
            for (int q = 0; q < 4; ++q) {
                u64 bb = ((const u64*)(sm + B1_OFF))[cc * 4 + q];
                c1a[q] = bb; c1b[q] = bb;
            }
            #pragma unroll
            for (int c = 0; c < 2; ++c)
                #pragma unroll
                for (int r = 0; r < 3; ++r)
                    #pragma unroll
                    for (int q3 = 0; q3 < 3; ++q3) {
                        int j = c * 9 + r * 3 + q3;
                        u64 pa0 = pack2(sm[ibase0 + c * 100 + r * 10 + q3]);
                        u64 pa1 = pack2(sm[ibase1 + c * 100 + r * 10 + q3]);
                        const ulonglong2* wv =
                            (const ulonglong2*)(sm + W1T_OFF + j * 32 + cc * 8);
                        ulonglong2 w0v = wv[0], w1v = wv[1];
                        ffma2(c1a[0], pa0, w0v.x); ffma2(c1a[1], pa0, w0v.y);
                        ffma2(c1a[2], pa0, w1v.x); ffma2(c1a[3], pa0, w1v.y);
                        ffma2(c1b[0], pa1, w0v.x); ffma2(c1b[1], pa1, w0v.y);
                        ffma2(c1b[2], pa1, w1v.x); ffma2(c1b[3], pa1, w1v.y);
                    }
            #pragma unroll
            for (int q = 0; q < 4; ++q) {
                float lo, hi;
                unpack2(lo, hi, c1a[q]);
                sm[hw0 + (2 * q) * 100]     = lo * normcdff(lo);
                sm[hw0 + (2 * q + 1) * 100] = hi * normcdff(hi);
                unpack2(lo, hi, c1b[q]);
                sm[hw1 + (2 * q) * 100]     = lo * normcdff(lo);
                sm[hw1 + (2 * q + 1) * 100] = hi * normcdff(hi);
            }
        }
        __syncthreads();

        // ---- conv2 partial over these 8 input channels ----
        const float* h1a = sm + H1C_OFF + (group * 2 + 0) * 800;
        const float* h1b = sm + H1C_OFF + (group * 2 + 1) * 800;
        #pragma unroll 1
        for (int icl = 0; icl < 8; ++icl) {
            float a0[9], a1[9];
            int base = icl * 100 + pbase;
            #pragma unroll
            for (int r = 0; r < 3; ++r)
                #pragma unroll
                for (int q3 = 0; q3 < 3; ++q3) {
                    a0[r * 3 + q3] = h1a[base + r * 10 + q3];
                    a1[r * 3 + q3] = h1b[base + r * 10 + q3];
                }
            const float* wrow = sm + W2T_OFF + (cc * 8 + icl) * 288;
            #pragma unroll
            for (int j = 0; j < 9; ++j) {
                u64 pa0 = pack2(a0[j]);
                u64 pa1 = pack2(a1[j]);
                const ulonglong2* wv = (const ulonglong2*)(wrow + j * 32);
                #pragma unroll
                for (int q = 0; q < 8; ++q) {
                    ulonglong2 w = wv[q];
                    ffma2(acc0[2 * q], pa0, w.x); ffma2(acc0[2 * q + 1], pa0, w.y);
                    ffma2(acc1[2 * q], pa1, w.x); ffma2(acc1[2 * q + 1], pa1, w.y);
                }
            }
        }
        __syncthreads();
    }

    // ---- GELU + fc dot per pixel, then mean over 64 pixels ----
    float sa = 0.0f, sb = 0.0f;
    #pragma unroll
    for (int q = 0; q < 16; ++q) {
        float f0 = sm[FC_OFF + 2 * q], f1 = sm[FC_OFF + 2 * q + 1];
        float lo, hi;
        unpack2(lo, hi, acc0[q]);
        sa = fmaf(lo * normcdff(lo), f0, sa);
        sa = fmaf(hi * normcdff(hi), f1, sa);
        unpack2(lo, hi, acc1[q]);
        sb = fmaf(lo * normcdff(lo), f0, sb);
        sb = fmaf(hi * normcdff(hi), f1, sb);
    }
    #pragma unroll
    for (int off = 16; off > 0; off >>= 1) {
        sa += __shfl_down_sync(0xffffffffu, sa, off);
        sb += __shfl_down_sync(0xffffffffu, sb, off);
    }
    int w = tid >> 5;  // warp 0..3
    if ((tid & 31) == 0) {
        sm[RED_OFF + (w >> 1) * 4 + (w & 1) * 2 + 0] = sa;
        sm[RED_OFF + (w >> 1) * 4 + (w & 1) * 2 + 1] = sb;
    }
    __syncthreads();
    if (tid < 4) {
        int grp = tid >> 1, sel = tid & 1;
        float v = sm[RED_OFF + grp * 4 + sel] + sm[RED_OFF + grp * 4 + 2 + sel];
        v = v * (1.0f / 64.0f) + sm[FCB_OFF];
        int tile = tile0 + tid;
        int b = tile / (KK * TT);
        int rem = tile - b * (KK * TT);
        int k = rem / TT;
        int t = rem - k * TT;
        out[(b * TT + t) * KK + k] = v;
    }
}

// ---------------- launch ----------------
extern "C" void kernel_launch(void* const* d_in, const int* in_sizes, int n_in,
                              void* d_out, int out_size) {
    const float* mu        = (const float*)d_in[0];
    const float* sigma0    = (const float*)d_in[1];
    const float* sigma_vel = (const float*)d_in[2];
    const float* amplitude = (const float*)d_in[3];
    const float* sh_base   = (const float*)d_in[4];
    const float* sh_vel    = (const float*)d_in[5];
    const float* p0        = (const float*)d_in[6];
    const float* p_vel     = (const float*)d_in[7];
    const float* tau_raw   = (const float*)d_in[8];
    const float* gam_raw   = (const float*)d_in[9];
    const float* limb_ra   = (const float*)d_in[10];
    const float* limb_la   = (const float*)d_in[11];
    const float* limb_ll   = (const float*)d_in[12];
    const float* chest     = (const float*)d_in[13];
    const float* conv1_w   = (const float*)d_in[14];
    const float* conv1_b   = (const float*)d_in[15];
    const float* conv2_w   = (const float*)d_in[16];
    const float* conv2_b   = (const float*)d_in[17];
    const float* fc_w      = (const float*)d_in[18];
    const float* fc_b      = (const float*)d_in[19];
    float* out = (float*)d_out;

    prep_kernel<<<1, 256>>>(limb_ra, limb_la, limb_ll, chest, conv1_w, conv2_w);
    splat_kernel<<<dim3(TT, BB), 384>>>(mu, sigma0, sigma_vel, amplitude,
                                        sh_base, sh_vel, p0, p_vel, tau_raw, gam_raw);
    size_t shbytes = SMEM_FLOATS * sizeof(float);
    cudaFuncSetAttribute(cnn_kernel, cudaFuncAttributeMaxDynamicSharedMemorySize, (int)shbytes);
    cnn_kernel<<<(BB * KK * TT) / 4, 128, shbytes>>>(conv1_b, conv2_b, fc_w, fc_b, out);
}